// round 1
// baseline (speedup 1.0000x reference)
#include <cuda_runtime.h>
#include <math.h>

#define B_   128
#define T_   256
#define D_   512
#define H_   1024
#define O_   1024
#define G4H  4096   // 4*H

// ---------------- scratch (static device globals; no allocations) ----------
__device__ float g_xproj[(size_t)B_ * T_ * G4H];  // [B,T,4H]  = 536.9 MB
__device__ float g_gates[B_ * G4H];               // [B,4H]    = 2 MB
__device__ float g_h[B_ * H_];
__device__ float g_c[B_ * H_];
__device__ float g_logits[B_ * O_];

// ---------------------------------------------------------------------------
// Kernel 1: xproj[b,t,g,h] = sum_d x[b,t,d] * Wx[g,h,d] + b[g,h]
// GEMM  C[M,N] = A[M,K] @ B[N,K]^T + bias[n],  M=32768, N=4096, K=512
// Tiling: BM=BN=128, BK=8, 256 threads, 8x8 micro-tile per thread.
// ---------------------------------------------------------------------------
__global__ __launch_bounds__(256)
void gemm_xproj_kernel(const float* __restrict__ A,
                       const float* __restrict__ Bm,
                       const float* __restrict__ bias,
                       int M, int N, int K)
{
    __shared__ float As[8][128];
    __shared__ float Bs[8][128];

    const int bn = blockIdx.x;       // N tile
    const int bm = blockIdx.y;       // M tile
    const int tid = threadIdx.x;
    const int tx = tid & 15;         // 0..15  (column group)
    const int ty = tid >> 4;         // 0..15  (row group)

    const float* Ab = A  + (size_t)bm * 128 * K;
    const float* Bb = Bm + (size_t)bn * 128 * K;

    const int lrow = tid >> 1;          // 0..127
    const int lk   = (tid & 1) * 4;     // 0 or 4

    float acc[8][8];
    #pragma unroll
    for (int i = 0; i < 8; i++)
        #pragma unroll
        for (int j = 0; j < 8; j++) acc[i][j] = 0.f;

    for (int k0 = 0; k0 < K; k0 += 8) {
        float4 av = *(const float4*)(Ab + (size_t)lrow * K + k0 + lk);
        float4 bv = *(const float4*)(Bb + (size_t)lrow * K + k0 + lk);
        As[lk + 0][lrow] = av.x; As[lk + 1][lrow] = av.y;
        As[lk + 2][lrow] = av.z; As[lk + 3][lrow] = av.w;
        Bs[lk + 0][lrow] = bv.x; Bs[lk + 1][lrow] = bv.y;
        Bs[lk + 2][lrow] = bv.z; Bs[lk + 3][lrow] = bv.w;
        __syncthreads();

        #pragma unroll
        for (int kk = 0; kk < 8; kk++) {
            float am[8], bnv[8];
            float4 a0 = *(const float4*)&As[kk][ty * 8];
            float4 a1 = *(const float4*)&As[kk][ty * 8 + 4];
            float4 b0 = *(const float4*)&Bs[kk][tx * 8];
            float4 b1 = *(const float4*)&Bs[kk][tx * 8 + 4];
            am[0]=a0.x; am[1]=a0.y; am[2]=a0.z; am[3]=a0.w;
            am[4]=a1.x; am[5]=a1.y; am[6]=a1.z; am[7]=a1.w;
            bnv[0]=b0.x; bnv[1]=b0.y; bnv[2]=b0.z; bnv[3]=b0.w;
            bnv[4]=b1.x; bnv[5]=b1.y; bnv[6]=b1.z; bnv[7]=b1.w;
            #pragma unroll
            for (int i = 0; i < 8; i++)
                #pragma unroll
                for (int j = 0; j < 8; j++)
                    acc[i][j] = fmaf(am[i], bnv[j], acc[i][j]);
        }
        __syncthreads();
    }

    const int row0 = bm * 128 + ty * 8;
    const int col0 = bn * 128 + tx * 8;
    #pragma unroll
    for (int i = 0; i < 8; i++) {
        #pragma unroll
        for (int j = 0; j < 8; j++) {
            g_xproj[(size_t)(row0 + i) * N + col0 + j] = acc[i][j] + bias[col0 + j];
        }
    }
}

// ---------------------------------------------------------------------------
// Recurrent / logits GEMM: C[m,n] = g_h[m,:] @ Bm[n,:]^T + add
//   MODE 0: N=4096, add = g_xproj[(m*T+t)*4096 + n], out = g_gates
//   MODE 1: N=1024, add = bias[n],                   out = g_logits
// Tiling: BM=BN=64, BK=16, 256 threads, 4x4 per thread. K = H_ = 1024.
// ---------------------------------------------------------------------------
template <int MODE>
__global__ __launch_bounds__(256)
void gemm_rec_kernel(const float* __restrict__ Bm,
                     const float* __restrict__ bias,
                     int N, int t)
{
    __shared__ float As[16][65];
    __shared__ float Bs[16][65];

    const int bn = blockIdx.x;
    const int bm = blockIdx.y;
    const int tid = threadIdx.x;
    const int tx = tid & 15;
    const int ty = tid >> 4;

    const float* Ab = g_h + (size_t)bm * 64 * H_;
    const float* Bb = Bm  + (size_t)bn * 64 * H_;

    const int lrow = tid >> 2;          // 0..63
    const int lk   = (tid & 3) * 4;     // 0,4,8,12

    float acc[4][4];
    #pragma unroll
    for (int i = 0; i < 4; i++)
        #pragma unroll
        for (int j = 0; j < 4; j++) acc[i][j] = 0.f;

    for (int k0 = 0; k0 < H_; k0 += 16) {
        float4 av = *(const float4*)(Ab + (size_t)lrow * H_ + k0 + lk);
        float4 bv = *(const float4*)(Bb + (size_t)lrow * H_ + k0 + lk);
        As[lk + 0][lrow] = av.x; As[lk + 1][lrow] = av.y;
        As[lk + 2][lrow] = av.z; As[lk + 3][lrow] = av.w;
        Bs[lk + 0][lrow] = bv.x; Bs[lk + 1][lrow] = bv.y;
        Bs[lk + 2][lrow] = bv.z; Bs[lk + 3][lrow] = bv.w;
        __syncthreads();

        #pragma unroll
        for (int kk = 0; kk < 16; kk++) {
            float am[4], bnv[4];
            #pragma unroll
            for (int i = 0; i < 4; i++) am[i]  = As[kk][ty * 4 + i];
            #pragma unroll
            for (int j = 0; j < 4; j++) bnv[j] = Bs[kk][tx * 4 + j];
            #pragma unroll
            for (int i = 0; i < 4; i++)
                #pragma unroll
                for (int j = 0; j < 4; j++)
                    acc[i][j] = fmaf(am[i], bnv[j], acc[i][j]);
        }
        __syncthreads();
    }

    const int row0 = bm * 64 + ty * 4;
    const int col0 = bn * 64 + tx * 4;
    #pragma unroll
    for (int i = 0; i < 4; i++) {
        #pragma unroll
        for (int j = 0; j < 4; j++) {
            if (MODE == 0) {
                g_gates[(size_t)(row0 + i) * G4H + col0 + j] =
                    acc[i][j] + g_xproj[((size_t)(row0 + i) * T_ + t) * G4H + col0 + j];
            } else {
                g_logits[(size_t)(row0 + i) * O_ + col0 + j] =
                    acc[i][j] + bias[col0 + j];
            }
        }
    }
}

// ---------------------------------------------------------------------------
// Elementwise LSTM cell update from g_gates -> g_h, g_c
// ---------------------------------------------------------------------------
__device__ __forceinline__ float sigmoidf_(float x) {
    return 1.f / (1.f + __expf(-x));
}

__global__ __launch_bounds__(256)
void lstm_update_kernel()
{
    int idx = blockIdx.x * blockDim.x + threadIdx.x;
    if (idx >= B_ * H_) return;
    int b = idx >> 10;       // /H_
    int o = idx & (H_ - 1);
    const float* gb = g_gates + (size_t)b * G4H;
    float i_t = sigmoidf_(gb[o]);
    float f_t = sigmoidf_(gb[H_ + o]);
    float g_t = tanhf(gb[2 * H_ + o]);
    float o_t = sigmoidf_(gb[3 * H_ + o]);
    float c   = f_t * g_c[idx] + i_t * g_t;
    g_c[idx] = c;
    g_h[idx] = o_t * tanhf(c);
}

__global__ void init_state_kernel()
{
    int idx = blockIdx.x * blockDim.x + threadIdx.x;
    if (idx < B_ * H_) { g_h[idx] = 0.f; g_c[idx] = 0.f; }
}

// ---------------------------------------------------------------------------
// Softmax over logits rows -> output
// ---------------------------------------------------------------------------
__global__ __launch_bounds__(256)
void softmax_kernel(float* __restrict__ out)
{
    __shared__ float red[256];
    const int b = blockIdx.x;
    const int tid = threadIdx.x;
    const float* lr = g_logits + (size_t)b * O_;

    float m = -INFINITY;
    for (int i = tid; i < O_; i += 256) m = fmaxf(m, lr[i]);
    red[tid] = m; __syncthreads();
    for (int s = 128; s > 0; s >>= 1) {
        if (tid < s) red[tid] = fmaxf(red[tid], red[tid + s]);
        __syncthreads();
    }
    m = red[0]; __syncthreads();

    float sum = 0.f;
    for (int i = tid; i < O_; i += 256) sum += expf(lr[i] - m);
    red[tid] = sum; __syncthreads();
    for (int s = 128; s > 0; s >>= 1) {
        if (tid < s) red[tid] += red[tid + s];
        __syncthreads();
    }
    float inv = 1.f / red[0];

    for (int i = tid; i < O_; i += 256)
        out[(size_t)b * O_ + i] = expf(lr[i] - m) * inv;
}

// ---------------------------------------------------------------------------
extern "C" void kernel_launch(void* const* d_in, const int* in_sizes, int n_in,
                              void* d_out, int out_size)
{
    const float* x   = (const float*)d_in[0];  // [B,T,D]
    const float* Wx  = (const float*)d_in[1];  // [4,H,D]
    const float* Wh  = (const float*)d_in[2];  // [4,H,H]
    const float* b   = (const float*)d_in[3];  // [4,H]
    const float* Whp = (const float*)d_in[4];  // [O,H]
    const float* bhp = (const float*)d_in[5];  // [O]
    float* out = (float*)d_out;

    // 1) xproj = x @ Wx^T + b   (M=B*T=32768, N=4096, K=512)
    {
        dim3 grid(G4H / 128, (B_ * T_) / 128);
        gemm_xproj_kernel<<<grid, 256>>>(x, Wx, b, B_ * T_, G4H, D_);
    }

    // 2) init recurrent state
    init_state_kernel<<<(B_ * H_ + 255) / 256, 256>>>();

    // 3) recurrence: 256 dependent steps
    for (int t = 0; t < T_; t++) {
        dim3 grid(G4H / 64, B_ / 64);   // 64 x 2 = 128 blocks
        gemm_rec_kernel<0><<<grid, 256>>>(Wh, nullptr, G4H, t);
        lstm_update_kernel<<<(B_ * H_ + 255) / 256, 256>>>();
    }

    // 4) logits = h_T @ Whp^T + bhp
    {
        dim3 grid(O_ / 64, B_ / 64);    // 16 x 2 = 32 blocks
        gemm_rec_kernel<1><<<grid, 256>>>(Whp, bhp, O_, 0);
    }

    // 5) softmax rows -> out
    softmax_kernel<<<B_, 256>>>(out);
}

// round 2
// speedup vs baseline: 1.7118x; 1.7118x over previous
#include <cuda_runtime.h>
#include <cuda_bf16.h>
#include <math.h>
#include <stdint.h>

#define B_   128
#define T_   256
#define D_   512
#define H_   1024
#define O_   1024
#define G4H  4096   // 4*H

// ---------------- scratch (static device globals; no allocations) ----------
__device__ float g_xproj[(size_t)B_ * T_ * G4H];   // [B,T,4,H]
__device__ float g_h[B_ * H_];
__device__ float g_c[B_ * H_];
__device__ float g_logits[B_ * O_];

__device__ __align__(16) __nv_bfloat16 g_x_hi[(size_t)B_ * T_ * D_];
__device__ __align__(16) __nv_bfloat16 g_x_lo[(size_t)B_ * T_ * D_];
__device__ __align__(16) __nv_bfloat16 g_Wx_hi[G4H * D_];
__device__ __align__(16) __nv_bfloat16 g_Wx_lo[G4H * D_];
__device__ __align__(16) __nv_bfloat16 g_Wh_hi[G4H * H_];
__device__ __align__(16) __nv_bfloat16 g_Wh_lo[G4H * H_];
__device__ __align__(16) __nv_bfloat16 g_h_hi[B_ * H_];
__device__ __align__(16) __nv_bfloat16 g_h_lo[B_ * H_];

// ---------------------------------------------------------------------------
// helpers
// ---------------------------------------------------------------------------
__device__ __forceinline__ uint32_t smem_u32(const void* p) {
    return (uint32_t)__cvta_generic_to_shared(p);
}

__device__ __forceinline__ void ldsm4(uint32_t& r0, uint32_t& r1, uint32_t& r2,
                                      uint32_t& r3, uint32_t a) {
    asm volatile("ldmatrix.sync.aligned.m8n8.x4.shared.b16 {%0,%1,%2,%3}, [%4];"
                 : "=r"(r0), "=r"(r1), "=r"(r2), "=r"(r3) : "r"(a));
}

__device__ __forceinline__ void mma16816(float* c,
                                         uint32_t a0, uint32_t a1, uint32_t a2, uint32_t a3,
                                         uint32_t b0, uint32_t b1) {
    asm volatile(
        "mma.sync.aligned.m16n8k16.row.col.f32.bf16.bf16.f32 "
        "{%0,%1,%2,%3}, {%4,%5,%6,%7}, {%8,%9}, {%0,%1,%2,%3};"
        : "+f"(c[0]), "+f"(c[1]), "+f"(c[2]), "+f"(c[3])
        : "r"(a0), "r"(a1), "r"(a2), "r"(a3), "r"(b0), "r"(b1));
}

__device__ __forceinline__ float sigmoidf_(float x) {
    return 1.f / (1.f + __expf(-x));
}

// ---------------------------------------------------------------------------
// Split fp32 -> (hi, lo) bf16
// ---------------------------------------------------------------------------
__global__ void split_kernel(const float* __restrict__ src,
                             __nv_bfloat16* __restrict__ hi,
                             __nv_bfloat16* __restrict__ lo, int n)
{
    int i = blockIdx.x * blockDim.x + threadIdx.x;
    if (i < n) {
        float v = src[i];
        __nv_bfloat16 h = __float2bfloat16(v);
        hi[i] = h;
        lo[i] = __float2bfloat16(v - __bfloat162float(h));
    }
}

__global__ void init_state_kernel()
{
    int idx = blockIdx.x * blockDim.x + threadIdx.x;
    if (idx < B_ * H_) {
        g_h[idx] = 0.f; g_c[idx] = 0.f;
        g_h_hi[idx] = __float2bfloat16(0.f);
        g_h_lo[idx] = __float2bfloat16(0.f);
    }
}

// ---------------------------------------------------------------------------
// Split-bf16 MMA GEMM:  C[M,N-tile] = A[M,K] @ B[N,K]^T  (fp32-accurate)
// CTA tile: M=128, N=32, KC=32.  256 threads = 8 warps (4 M x 2 N).
// MODE 0: recurrence step, fused LSTM update epilogue.
//         A = g_h_hi/lo (K=1024). N-tile = 8 h-cols x 4 gates (gate-strided B rows).
// MODE 1: xproj GEMM. A = g_x_hi/lo (K=512). Contiguous 32-col N-tile,
//         epilogue writes g_xproj + bias.
// ---------------------------------------------------------------------------
template <int MODE>
__global__ __launch_bounds__(256)
void mma_gemm_kernel(const __nv_bfloat16* __restrict__ Ahi,
                     const __nv_bfloat16* __restrict__ Alo,
                     const __nv_bfloat16* __restrict__ Bhi,
                     const __nv_bfloat16* __restrict__ Blo,
                     const float* __restrict__ bias,
                     int K, int t)
{
    __shared__ __align__(16) __nv_bfloat16 As_hi[128 * 40];
    __shared__ __align__(16) __nv_bfloat16 As_lo[128 * 40];
    __shared__ __align__(16) __nv_bfloat16 Bs_hi[32 * 40];
    __shared__ __align__(16) __nv_bfloat16 Bs_lo[32 * 40];
    __shared__ float gates[128 * 33];   // used only in MODE 0

    const int tid  = threadIdx.x;
    const int lane = tid & 31;
    const int w    = tid >> 5;
    const int mw   = w >> 1;            // 0..3
    const int nw   = w & 1;             // 0..1
    const int m_base = mw * 32;
    const int n_base = nw * 16;
    const int m_off  = (MODE == 1) ? blockIdx.y * 128 : 0;
    const int col0   = (MODE == 0) ? blockIdx.x * 8 : 0;   // h-col group (MODE 0)

    float acc[2][2][4];
    #pragma unroll
    for (int mi = 0; mi < 2; mi++)
        #pragma unroll
        for (int ni = 0; ni < 2; ni++)
            #pragma unroll
            for (int r = 0; r < 4; r++) acc[mi][ni][r] = 0.f;

    for (int k0 = 0; k0 < K; k0 += 32) {
        // ---- load A chunk: 128 rows x 32 cols, hi & lo ----
        #pragma unroll
        for (int ii = 0; ii < 2; ii++) {
            int i = tid + ii * 256;          // 0..511
            int row = i >> 2, q = i & 3;
            const uint4* sh = (const uint4*)(Ahi + (size_t)(m_off + row) * K + k0) + q;
            const uint4* sl = (const uint4*)(Alo + (size_t)(m_off + row) * K + k0) + q;
            *(((uint4*)(As_hi + row * 40)) + q) = *sh;
            *(((uint4*)(As_lo + row * 40)) + q) = *sl;
        }
        // ---- load B chunk: 32 rows x 32 cols, hi & lo ----
        {
            int i = tid;                     // 0..255; split = i>>7
            int rr = (i & 127) >> 2, q = i & 3;
            int n;
            if (MODE == 0) n = (rr >> 3) * H_ + col0 + (rr & 7);
            else           n = blockIdx.x * 32 + rr;
            if (i < 128) {
                const uint4* s = (const uint4*)(Bhi + (size_t)n * K + k0) + q;
                *(((uint4*)(Bs_hi + rr * 40)) + q) = *s;
            } else {
                const uint4* s = (const uint4*)(Blo + (size_t)n * K + k0) + q;
                *(((uint4*)(Bs_lo + rr * 40)) + q) = *s;
            }
        }
        __syncthreads();

        // ---- compute: two k16 sub-steps ----
        #pragma unroll
        for (int kk = 0; kk < 32; kk += 16) {
            uint32_t ah[2][4], al[2][4], bh[4], bl[4];
            // A fragments (16x16 per m-tile)
            {
                int arow = (lane & 15);
                int acol = kk + ((lane >> 4) << 3);
                #pragma unroll
                for (int mi = 0; mi < 2; mi++) {
                    int r = m_base + mi * 16 + arow;
                    uint32_t ad = smem_u32(As_hi + r * 40 + acol);
                    ldsm4(ah[mi][0], ah[mi][1], ah[mi][2], ah[mi][3], ad);
                    uint32_t ad2 = smem_u32(As_lo + r * 40 + acol);
                    ldsm4(al[mi][0], al[mi][1], al[mi][2], al[mi][3], ad2);
                }
            }
            // B fragments (two n8 tiles in one x4)
            {
                int brow = n_base + ((lane >> 4) << 3) + (lane & 7);
                int bcol = kk + (((lane >> 3) & 1) << 3);
                uint32_t bd = smem_u32(Bs_hi + brow * 40 + bcol);
                ldsm4(bh[0], bh[1], bh[2], bh[3], bd);
                uint32_t bd2 = smem_u32(Bs_lo + brow * 40 + bcol);
                ldsm4(bl[0], bl[1], bl[2], bl[3], bd2);
            }
            #pragma unroll
            for (int mi = 0; mi < 2; mi++)
                #pragma unroll
                for (int ni = 0; ni < 2; ni++) {
                    mma16816(acc[mi][ni], ah[mi][0], ah[mi][1], ah[mi][2], ah[mi][3],
                             bh[ni * 2], bh[ni * 2 + 1]);
                    mma16816(acc[mi][ni], ah[mi][0], ah[mi][1], ah[mi][2], ah[mi][3],
                             bl[ni * 2], bl[ni * 2 + 1]);
                    mma16816(acc[mi][ni], al[mi][0], al[mi][1], al[mi][2], al[mi][3],
                             bh[ni * 2], bh[ni * 2 + 1]);
                }
        }
        __syncthreads();
    }

    if (MODE == 1) {
        // ---- epilogue: write g_xproj + bias ----
        #pragma unroll
        for (int mi = 0; mi < 2; mi++) {
            #pragma unroll
            for (int ni = 0; ni < 2; ni++) {
                int grow = m_off + m_base + mi * 16 + (lane >> 2);
                int gcol = blockIdx.x * 32 + n_base + ni * 8 + ((lane & 3) << 1);
                float b0 = bias[gcol], b1 = bias[gcol + 1];
                float* p0 = g_xproj + (size_t)grow * G4H + gcol;
                p0[0] = acc[mi][ni][0] + b0;
                p0[1] = acc[mi][ni][1] + b1;
                float* p1 = g_xproj + (size_t)(grow + 8) * G4H + gcol;
                p1[0] = acc[mi][ni][2] + b0;
                p1[1] = acc[mi][ni][3] + b1;
            }
        }
    } else {
        // ---- epilogue: stage gates to smem, fused LSTM update ----
        #pragma unroll
        for (int mi = 0; mi < 2; mi++) {
            #pragma unroll
            for (int ni = 0; ni < 2; ni++) {
                int row = m_base + mi * 16 + (lane >> 2);
                int col = n_base + ni * 8 + ((lane & 3) << 1);
                gates[row * 33 + col]           = acc[mi][ni][0];
                gates[row * 33 + col + 1]       = acc[mi][ni][1];
                gates[(row + 8) * 33 + col]     = acc[mi][ni][2];
                gates[(row + 8) * 33 + col + 1] = acc[mi][ni][3];
            }
        }
        __syncthreads();

        #pragma unroll
        for (int e = tid; e < 1024; e += 256) {
            int b  = e >> 3;
            int hc = e & 7;
            int colg = col0 + hc;
            const size_t xbase = ((size_t)b * T_ + t) * G4H;
            float gi = gates[b * 33 + hc]      + g_xproj[xbase + colg];
            float gf = gates[b * 33 + 8 + hc]  + g_xproj[xbase + H_ + colg];
            float gg = gates[b * 33 + 16 + hc] + g_xproj[xbase + 2 * H_ + colg];
            float go = gates[b * 33 + 24 + hc] + g_xproj[xbase + 3 * H_ + colg];
            float it = sigmoidf_(gi);
            float ft = sigmoidf_(gf);
            float gt = tanhf(gg);
            float ot = sigmoidf_(go);
            int idx = b * H_ + colg;
            float c = ft * g_c[idx] + it * gt;
            g_c[idx] = c;
            float h = ot * tanhf(c);
            g_h[idx] = h;
            __nv_bfloat16 hh = __float2bfloat16(h);
            g_h_hi[idx] = hh;
            g_h_lo[idx] = __float2bfloat16(h - __bfloat162float(hh));
        }
    }
}

// ---------------------------------------------------------------------------
// Logits GEMM (fp32, tiny): C[128,1024] = g_h @ Whp^T + bhp
// ---------------------------------------------------------------------------
__global__ __launch_bounds__(256)
void logits_gemm_kernel(const float* __restrict__ Bm,
                        const float* __restrict__ bias)
{
    __shared__ float As[16][65];
    __shared__ float Bs[16][65];

    const int bn = blockIdx.x;
    const int bm = blockIdx.y;
    const int tid = threadIdx.x;
    const int tx = tid & 15;
    const int ty = tid >> 4;

    const float* Ab = g_h + (size_t)bm * 64 * H_;
    const float* Bb = Bm  + (size_t)bn * 64 * H_;

    const int lrow = tid >> 2;
    const int lk   = (tid & 3) * 4;

    float acc[4][4];
    #pragma unroll
    for (int i = 0; i < 4; i++)
        #pragma unroll
        for (int j = 0; j < 4; j++) acc[i][j] = 0.f;

    for (int k0 = 0; k0 < H_; k0 += 16) {
        float4 av = *(const float4*)(Ab + (size_t)lrow * H_ + k0 + lk);
        float4 bv = *(const float4*)(Bb + (size_t)lrow * H_ + k0 + lk);
        As[lk + 0][lrow] = av.x; As[lk + 1][lrow] = av.y;
        As[lk + 2][lrow] = av.z; As[lk + 3][lrow] = av.w;
        Bs[lk + 0][lrow] = bv.x; Bs[lk + 1][lrow] = bv.y;
        Bs[lk + 2][lrow] = bv.z; Bs[lk + 3][lrow] = bv.w;
        __syncthreads();

        #pragma unroll
        for (int kk = 0; kk < 16; kk++) {
            float am[4], bnv[4];
            #pragma unroll
            for (int i = 0; i < 4; i++) am[i]  = As[kk][ty * 4 + i];
            #pragma unroll
            for (int j = 0; j < 4; j++) bnv[j] = Bs[kk][tx * 4 + j];
            #pragma unroll
            for (int i = 0; i < 4; i++)
                #pragma unroll
                for (int j = 0; j < 4; j++)
                    acc[i][j] = fmaf(am[i], bnv[j], acc[i][j]);
        }
        __syncthreads();
    }

    const int row0 = bm * 64 + ty * 4;
    const int col0 = bn * 64 + tx * 4;
    #pragma unroll
    for (int i = 0; i < 4; i++)
        #pragma unroll
        for (int j = 0; j < 4; j++)
            g_logits[(size_t)(row0 + i) * O_ + col0 + j] = acc[i][j] + bias[col0 + j];
}

// ---------------------------------------------------------------------------
// Softmax rows -> output
// ---------------------------------------------------------------------------
__global__ __launch_bounds__(256)
void softmax_kernel(float* __restrict__ out)
{
    __shared__ float red[256];
    const int b = blockIdx.x;
    const int tid = threadIdx.x;
    const float* lr = g_logits + (size_t)b * O_;

    float m = -INFINITY;
    for (int i = tid; i < O_; i += 256) m = fmaxf(m, lr[i]);
    red[tid] = m; __syncthreads();
    for (int s = 128; s > 0; s >>= 1) {
        if (tid < s) red[tid] = fmaxf(red[tid], red[tid + s]);
        __syncthreads();
    }
    m = red[0]; __syncthreads();

    float sum = 0.f;
    for (int i = tid; i < O_; i += 256) sum += expf(lr[i] - m);
    red[tid] = sum; __syncthreads();
    for (int s = 128; s > 0; s >>= 1) {
        if (tid < s) red[tid] += red[tid + s];
        __syncthreads();
    }
    float inv = 1.f / red[0];

    for (int i = tid; i < O_; i += 256)
        out[(size_t)b * O_ + i] = expf(lr[i] - m) * inv;
}

// ---------------------------------------------------------------------------
extern "C" void kernel_launch(void* const* d_in, const int* in_sizes, int n_in,
                              void* d_out, int out_size)
{
    const float* x   = (const float*)d_in[0];  // [B,T,D]
    const float* Wx  = (const float*)d_in[1];  // [4,H,D]
    const float* Wh  = (const float*)d_in[2];  // [4,H,H]
    const float* b   = (const float*)d_in[3];  // [4,H]
    const float* Whp = (const float*)d_in[4];  // [O,H]
    const float* bhp = (const float*)d_in[5];  // [O]
    float* out = (float*)d_out;

    __nv_bfloat16 *x_hi, *x_lo, *wx_hi, *wx_lo, *wh_hi, *wh_lo;
    cudaGetSymbolAddress((void**)&x_hi,  g_x_hi);
    cudaGetSymbolAddress((void**)&x_lo,  g_x_lo);
    cudaGetSymbolAddress((void**)&wx_hi, g_Wx_hi);
    cudaGetSymbolAddress((void**)&wx_lo, g_Wx_lo);
    cudaGetSymbolAddress((void**)&wh_hi, g_Wh_hi);
    cudaGetSymbolAddress((void**)&wh_lo, g_Wh_lo);

    // 1) split inputs into bf16 hi/lo pairs
    {
        int nx = B_ * T_ * D_;
        split_kernel<<<(nx + 255) / 256, 256>>>(x, x_hi, x_lo, nx);
        int nwx = G4H * D_;
        split_kernel<<<(nwx + 255) / 256, 256>>>(Wx, wx_hi, wx_lo, nwx);
        int nwh = G4H * H_;
        split_kernel<<<(nwh + 255) / 256, 256>>>(Wh, wh_hi, wh_lo, nwh);
    }

    // 2) xproj = x @ Wx^T + b  via split-bf16 MMA
    {
        dim3 grid(G4H / 32, (B_ * T_) / 128);
        mma_gemm_kernel<1><<<grid, 256>>>(x_hi, x_lo, wx_hi, wx_lo, b, D_, 0);
    }

    // 3) init state
    init_state_kernel<<<(B_ * H_ + 255) / 256, 256>>>();

    // 4) recurrence: one fused GEMM+update kernel per step
    __nv_bfloat16 *h_hi, *h_lo;
    cudaGetSymbolAddress((void**)&h_hi, g_h_hi);
    cudaGetSymbolAddress((void**)&h_lo, g_h_lo);
    for (int t = 0; t < T_; t++) {
        mma_gemm_kernel<0><<<H_ / 8, 256>>>(h_hi, h_lo, wh_hi, wh_lo, nullptr, H_, t);
    }

    // 5) logits + softmax
    {
        dim3 grid(O_ / 64, B_ / 64);
        logits_gemm_kernel<<<grid, 256>>>(Whp, bhp);
    }
    softmax_kernel<<<B_, 256>>>(out);
}

// round 3
// speedup vs baseline: 4.1396x; 2.4182x over previous
#include <cuda_runtime.h>
#include <cuda_fp16.h>
#include <math.h>
#include <stdint.h>

#define B_   128
#define T_   256
#define D_   512
#define H_   1024
#define O_   1024
#define G4H  4096
#define NCTA 128

// ---------------- scratch (static device globals; no allocations) ----------
__device__ float g_xproj[(size_t)B_ * T_ * G4H];   // [B,T,4,H]
__device__ float g_h[B_ * H_];
__device__ float g_c[B_ * H_];
__device__ float g_logits[B_ * O_];
__device__ unsigned g_bar;

__device__ __align__(16) __half g_x16[(size_t)B_ * T_ * D_];
__device__ __align__(16) __half g_Wx_hi[G4H * D_];
__device__ __align__(16) __half g_Wx_lo[G4H * D_];
__device__ __align__(16) __half g_Wh_hi[G4H * H_];
__device__ __align__(16) __half g_Wh_lo[G4H * H_];
__device__ __align__(16) __half g_h16[2 * B_ * H_];   // ping-pong h (fp16)

// ---------------------------------------------------------------------------
// helpers
// ---------------------------------------------------------------------------
__device__ __forceinline__ uint32_t smem_u32(const void* p) {
    return (uint32_t)__cvta_generic_to_shared(p);
}

__device__ __forceinline__ void ldsm4(uint32_t& r0, uint32_t& r1, uint32_t& r2,
                                      uint32_t& r3, uint32_t a) {
    asm volatile("ldmatrix.sync.aligned.m8n8.x4.shared.b16 {%0,%1,%2,%3}, [%4];"
                 : "=r"(r0), "=r"(r1), "=r"(r2), "=r"(r3) : "r"(a));
}

__device__ __forceinline__ void mma_f16(float* c, const uint32_t* a,
                                        uint32_t b0, uint32_t b1) {
    asm volatile(
        "mma.sync.aligned.m16n8k16.row.col.f32.f16.f16.f32 "
        "{%0,%1,%2,%3}, {%4,%5,%6,%7}, {%8,%9}, {%0,%1,%2,%3};"
        : "+f"(c[0]), "+f"(c[1]), "+f"(c[2]), "+f"(c[3])
        : "r"(a[0]), "r"(a[1]), "r"(a[2]), "r"(a[3]), "r"(b0), "r"(b1));
}

__device__ __forceinline__ void cp_async16(uint32_t dst, const void* src) {
    asm volatile("cp.async.cg.shared.global [%0], [%1], 16;" :: "r"(dst), "l"(src));
}
__device__ __forceinline__ void cp_async8(uint32_t dst, const void* src) {
    asm volatile("cp.async.ca.shared.global [%0], [%1], 8;" :: "r"(dst), "l"(src));
}
__device__ __forceinline__ void cp_commit() {
    asm volatile("cp.async.commit_group;");
}
template <int N> __device__ __forceinline__ void cp_wait() {
    asm volatile("cp.async.wait_group %0;" :: "n"(N));
}

__device__ __forceinline__ float sigmoidf_(float x) {
    return 1.f / (1.f + __expf(-x));
}

// ---------------------------------------------------------------------------
// conversion kernels
// ---------------------------------------------------------------------------
__global__ void cvt16_kernel(const float* __restrict__ src,
                             __half* __restrict__ dst, int n)
{
    int i = blockIdx.x * blockDim.x + threadIdx.x;
    if (i < n) dst[i] = __float2half(src[i]);
}

__global__ void split16_kernel(const float* __restrict__ src,
                               __half* __restrict__ hi,
                               __half* __restrict__ lo, int n)
{
    int i = blockIdx.x * blockDim.x + threadIdx.x;
    if (i < n) {
        float v = src[i];
        __half h = __float2half(v);
        hi[i] = h;
        lo[i] = __float2half(v - __half2float(h));
    }
}

__global__ void init_kernel()
{
    int i = blockIdx.x * blockDim.x + threadIdx.x;
    if (i < B_ * H_) g_c[i] = 0.f;
    if (i < 2 * B_ * H_) g_h16[i] = __float2half(0.f);
    if (i == 0) g_bar = 0;
}

// ---------------------------------------------------------------------------
// xproj GEMM:  xproj[m, n] = x16[m,:] @ (Wx_hi+Wx_lo)[n,:]^T + bias[n]
// M=32768, N=4096, K=512. CTA tile M128 N32 K32, 256 threads (4M x 2N warps).
// A single fp16, B hi/lo -> 2 MMAs per (mi,ni,k16).
// ---------------------------------------------------------------------------
__global__ __launch_bounds__(256)
void xproj_kernel(const float* __restrict__ bias)
{
    __shared__ __align__(16) __half As[128 * 40];
    __shared__ __align__(16) __half Bs_hi[32 * 40];
    __shared__ __align__(16) __half Bs_lo[32 * 40];

    const int tid  = threadIdx.x;
    const int lane = tid & 31;
    const int w    = tid >> 5;
    const int mw   = w >> 1;
    const int nw   = w & 1;
    const int m_base = mw * 32;
    const int n_base = nw * 16;
    const int m_off  = blockIdx.y * 128;
    const int n0     = blockIdx.x * 32;

    float acc[2][2][4];
    #pragma unroll
    for (int mi = 0; mi < 2; mi++)
        #pragma unroll
        for (int ni = 0; ni < 2; ni++)
            #pragma unroll
            for (int r = 0; r < 4; r++) acc[mi][ni][r] = 0.f;

    for (int k0 = 0; k0 < D_; k0 += 32) {
        #pragma unroll
        for (int ii = 0; ii < 2; ii++) {
            int i = tid + ii * 256;
            int row = i >> 2, q = i & 3;
            *(((uint4*)(As + row * 40)) + q) =
                *((const uint4*)(g_x16 + (size_t)(m_off + row) * D_ + k0) + q);
        }
        {
            int rr = (tid & 127) >> 2, q = tid & 3;
            int n = n0 + rr;
            if (tid < 128)
                *(((uint4*)(Bs_hi + rr * 40)) + q) =
                    *((const uint4*)(g_Wx_hi + (size_t)n * D_ + k0) + q);
            else
                *(((uint4*)(Bs_lo + rr * 40)) + q) =
                    *((const uint4*)(g_Wx_lo + (size_t)n * D_ + k0) + q);
        }
        __syncthreads();

        #pragma unroll
        for (int kk = 0; kk < 32; kk += 16) {
            uint32_t a[2][4], bh[4], bl[4];
            int arow = lane & 15;
            int acol = kk + ((lane >> 4) << 3);
            #pragma unroll
            for (int mi = 0; mi < 2; mi++) {
                uint32_t ad = smem_u32(As + (m_base + mi * 16 + arow) * 40 + acol);
                ldsm4(a[mi][0], a[mi][1], a[mi][2], a[mi][3], ad);
            }
            int brow = n_base + ((lane >> 4) << 3) + (lane & 7);
            int bcol = kk + (((lane >> 3) & 1) << 3);
            ldsm4(bh[0], bh[1], bh[2], bh[3], smem_u32(Bs_hi + brow * 40 + bcol));
            ldsm4(bl[0], bl[1], bl[2], bl[3], smem_u32(Bs_lo + brow * 40 + bcol));
            #pragma unroll
            for (int mi = 0; mi < 2; mi++)
                #pragma unroll
                for (int ni = 0; ni < 2; ni++) {
                    mma_f16(acc[mi][ni], a[mi], bh[ni * 2], bh[ni * 2 + 1]);
                    mma_f16(acc[mi][ni], a[mi], bl[ni * 2], bl[ni * 2 + 1]);
                }
        }
        __syncthreads();
    }

    #pragma unroll
    for (int mi = 0; mi < 2; mi++) {
        #pragma unroll
        for (int ni = 0; ni < 2; ni++) {
            int grow = m_off + m_base + mi * 16 + (lane >> 2);
            int gcol = n0 + n_base + ni * 8 + ((lane & 3) << 1);
            float b0 = bias[gcol], b1 = bias[gcol + 1];
            float* p0 = g_xproj + (size_t)grow * G4H + gcol;
            p0[0] = acc[mi][ni][0] + b0;
            p0[1] = acc[mi][ni][1] + b1;
            float* p1 = g_xproj + (size_t)(grow + 8) * G4H + gcol;
            p1[0] = acc[mi][ni][2] + b0;
            p1[1] = acc[mi][ni][3] + b1;
        }
    }
}

// ---------------------------------------------------------------------------
// Persistent LSTM recurrence kernel.
// 128 CTAs x 128 threads. CTA owns 8 h-cols x 4 gates (32 Wh rows, gate-major:
// smem B row r -> global Wh row (r>>3)*H + col0 + (r&7), so N dim = g*8+hc).
// Wh hi/lo resident in SMEM (128KB). h (fp16, single) streamed per step via
// cp.async double buffer (K_chunk=64). Software grid barrier per step.
// Warp layout 4M x 1N: warp tile m32 n32.
// ---------------------------------------------------------------------------
#define WH_SPLIT_SZ (32 * 1032 * 2)            // 66048 B per split
#define AS_OFF      (2 * WH_SPLIT_SZ)          // 132096
#define AS_BUF_SZ   (128 * 72 * 2)             // 18432 B per buffer
#define XP_OFF      (AS_OFF + 2 * AS_BUF_SZ)   // 168960
#define SMEM_LSTM   (XP_OFF + 128 * 34 * 4)    // 186368

__device__ __forceinline__ void load_chunk(uint32_t sbase, const __half* hin,
                                           int ch, int buf)
{
    const int tid = threadIdx.x;
    #pragma unroll
    for (int i = 0; i < 8; i++) {
        int idx = tid + i * 128;        // 0..1023
        int r = idx >> 3, c = idx & 7;
        cp_async16(sbase + AS_OFF + buf * AS_BUF_SZ + r * 144 + c * 16,
                   hin + (size_t)r * H_ + ch * 64 + c * 8);
    }
}

__global__ __launch_bounds__(128, 1)
void lstm_persistent_kernel()
{
    extern __shared__ char sm[];
    const int tid  = threadIdx.x;
    const int lane = tid & 31;
    const int w    = tid >> 5;
    const int col0 = blockIdx.x * 8;
    const uint32_t sbase = smem_u32(sm);

    // ---- resident Wh load (hi/lo), group 0 ----
    for (int i = tid; i < 8192; i += 128) {
        int s = i >> 12;
        int r = (i >> 7) & 31;
        int c = i & 127;
        int ng = (r >> 3) * H_ + col0 + (r & 7);
        const __half* src = (s ? g_Wh_lo : g_Wh_hi) + (size_t)ng * H_ + c * 8;
        cp_async16(sbase + s * WH_SPLIT_SZ + r * 2064 + c * 16, src);
    }
    cp_commit();

    for (int t = 0; t < T_; ++t) {
        const __half* hin = g_h16 + (size_t)(t & 1) * (B_ * H_);

        // ---- xproj slice prefetch (this thread's own cells) ----
        {
            int q2 = (lane & 3) * 2;
            #pragma unroll
            for (int mi = 0; mi < 2; mi++)
                #pragma unroll
                for (int ro = 0; ro < 2; ro++) {
                    int b = w * 32 + mi * 16 + ro * 8 + (lane >> 2);
                    #pragma unroll
                    for (int g = 0; g < 4; g++) {
                        const float* src = g_xproj +
                            (((size_t)b * T_ + t) * 4 + g) * H_ + col0 + q2;
                        cp_async8(sbase + XP_OFF + (b * 34 + g * 8 + q2) * 4, src);
                    }
                }
        }
        cp_commit();

        load_chunk(sbase, hin, 0, 0);
        cp_commit();

        float acc[2][4][4];
        #pragma unroll
        for (int mi = 0; mi < 2; mi++)
            #pragma unroll
            for (int ni = 0; ni < 4; ni++)
                #pragma unroll
                for (int r = 0; r < 4; r++) acc[mi][ni][r] = 0.f;

        for (int ch = 0; ch < 16; ++ch) {
            if (ch < 15) {
                load_chunk(sbase, hin, ch + 1, (ch + 1) & 1);
                cp_commit();
                cp_wait<1>();
            } else {
                cp_wait<0>();
            }
            __syncthreads();

            #pragma unroll
            for (int kk = 0; kk < 64; kk += 16) {
                uint32_t a[2][4];
                #pragma unroll
                for (int mi = 0; mi < 2; mi++) {
                    uint32_t ad = sbase + AS_OFF + (ch & 1) * AS_BUF_SZ
                                + (w * 32 + mi * 16 + (lane & 15)) * 144
                                + (kk + ((lane >> 4) << 3)) * 2;
                    ldsm4(a[mi][0], a[mi][1], a[mi][2], a[mi][3], ad);
                }
                uint32_t bh[4][2], bl[4][2];
                #pragma unroll
                for (int nh = 0; nh < 2; nh++) {
                    int row = nh * 16 + ((lane >> 4) << 3) + (lane & 7);
                    int cb  = (ch * 64 + kk + (((lane >> 3) & 1) << 3)) * 2;
                    uint32_t b0 = sbase + row * 2064 + cb;
                    ldsm4(bh[nh * 2][0], bh[nh * 2][1],
                          bh[nh * 2 + 1][0], bh[nh * 2 + 1][1], b0);
                    ldsm4(bl[nh * 2][0], bl[nh * 2][1],
                          bl[nh * 2 + 1][0], bl[nh * 2 + 1][1], b0 + WH_SPLIT_SZ);
                }
                #pragma unroll
                for (int mi = 0; mi < 2; mi++)
                    #pragma unroll
                    for (int ni = 0; ni < 4; ni++) {
                        mma_f16(acc[mi][ni], a[mi], bh[ni][0], bh[ni][1]);
                        mma_f16(acc[mi][ni], a[mi], bl[ni][0], bl[ni][1]);
                    }
            }
            __syncthreads();
        }

        // ---- register-resident LSTM epilogue ----
        __half* hout = g_h16 + (size_t)((t + 1) & 1) * (B_ * H_);
        const float* xps = (const float*)(sm + XP_OFF);
        #pragma unroll
        for (int mi = 0; mi < 2; mi++)
            #pragma unroll
            for (int ro = 0; ro < 2; ro++) {
                int b  = w * 32 + mi * 16 + ro * 8 + (lane >> 2);
                int q2 = (lane & 3) * 2;
                const float* xpb = xps + b * 34;
                int idx = b * H_ + col0 + q2;
                float2 cold = *(const float2*)(g_c + idx);
                float cv[2], hv[2];
                #pragma unroll
                for (int j = 0; j < 2; j++) {
                    int f = ro * 2 + j;
                    float gi = acc[mi][0][f] + xpb[q2 + j];
                    float gf = acc[mi][1][f] + xpb[8 + q2 + j];
                    float gg = acc[mi][2][f] + xpb[16 + q2 + j];
                    float go = acc[mi][3][f] + xpb[24 + q2 + j];
                    float it = sigmoidf_(gi);
                    float ft = sigmoidf_(gf);
                    float gt = tanhf(gg);
                    float ot = sigmoidf_(go);
                    float c  = ft * (j ? cold.y : cold.x) + it * gt;
                    cv[j] = c;
                    hv[j] = ot * tanhf(c);
                }
                *(float2*)(g_c + idx) = make_float2(cv[0], cv[1]);
                *(__half2*)(hout + idx) = __floats2half2_rn(hv[0], hv[1]);
                if (t == T_ - 1)
                    *(float2*)(g_h + idx) = make_float2(hv[0], hv[1]);
            }

        // ---- software grid barrier ----
        __syncthreads();
        if (tid == 0) {
            __threadfence();
            atomicAdd(&g_bar, 1u);
            unsigned tgt = (unsigned)NCTA * (t + 1);
            unsigned v;
            do {
                asm volatile("ld.acquire.gpu.u32 %0, [%1];" : "=r"(v) : "l"(&g_bar));
            } while (v < tgt);
        }
        __syncthreads();
    }
}

// ---------------------------------------------------------------------------
// Logits GEMM (fp32): C[128,1024] = g_h @ Whp^T + bhp
// ---------------------------------------------------------------------------
__global__ __launch_bounds__(256)
void logits_gemm_kernel(const float* __restrict__ Bm,
                        const float* __restrict__ bias)
{
    __shared__ float As[16][65];
    __shared__ float Bs[16][65];

    const int bn = blockIdx.x;
    const int bm = blockIdx.y;
    const int tid = threadIdx.x;
    const int tx = tid & 15;
    const int ty = tid >> 4;

    const float* Ab = g_h + (size_t)bm * 64 * H_;
    const float* Bb = Bm  + (size_t)bn * 64 * H_;

    const int lrow = tid >> 2;
    const int lk   = (tid & 3) * 4;

    float acc[4][4];
    #pragma unroll
    for (int i = 0; i < 4; i++)
        #pragma unroll
        for (int j = 0; j < 4; j++) acc[i][j] = 0.f;

    for (int k0 = 0; k0 < H_; k0 += 16) {
        float4 av = *(const float4*)(Ab + (size_t)lrow * H_ + k0 + lk);
        float4 bv = *(const float4*)(Bb + (size_t)lrow * H_ + k0 + lk);
        As[lk + 0][lrow] = av.x; As[lk + 1][lrow] = av.y;
        As[lk + 2][lrow] = av.z; As[lk + 3][lrow] = av.w;
        Bs[lk + 0][lrow] = bv.x; Bs[lk + 1][lrow] = bv.y;
        Bs[lk + 2][lrow] = bv.z; Bs[lk + 3][lrow] = bv.w;
        __syncthreads();

        #pragma unroll
        for (int kk = 0; kk < 16; kk++) {
            float am[4], bnv[4];
            #pragma unroll
            for (int i = 0; i < 4; i++) am[i]  = As[kk][ty * 4 + i];
            #pragma unroll
            for (int j = 0; j < 4; j++) bnv[j] = Bs[kk][tx * 4 + j];
            #pragma unroll
            for (int i = 0; i < 4; i++)
                #pragma unroll
                for (int j = 0; j < 4; j++)
                    acc[i][j] = fmaf(am[i], bnv[j], acc[i][j]);
        }
        __syncthreads();
    }

    const int row0 = bm * 64 + ty * 4;
    const int col0 = bn * 64 + tx * 4;
    #pragma unroll
    for (int i = 0; i < 4; i++)
        #pragma unroll
        for (int j = 0; j < 4; j++)
            g_logits[(size_t)(row0 + i) * O_ + col0 + j] = acc[i][j] + bias[col0 + j];
}

// ---------------------------------------------------------------------------
// Softmax rows -> output
// ---------------------------------------------------------------------------
__global__ __launch_bounds__(256)
void softmax_kernel(float* __restrict__ out)
{
    __shared__ float red[256];
    const int b = blockIdx.x;
    const int tid = threadIdx.x;
    const float* lr = g_logits + (size_t)b * O_;

    float m = -INFINITY;
    for (int i = tid; i < O_; i += 256) m = fmaxf(m, lr[i]);
    red[tid] = m; __syncthreads();
    for (int s = 128; s > 0; s >>= 1) {
        if (tid < s) red[tid] = fmaxf(red[tid], red[tid + s]);
        __syncthreads();
    }
    m = red[0]; __syncthreads();

    float sum = 0.f;
    for (int i = tid; i < O_; i += 256) sum += expf(lr[i] - m);
    red[tid] = sum; __syncthreads();
    for (int s = 128; s > 0; s >>= 1) {
        if (tid < s) red[tid] += red[tid + s];
        __syncthreads();
    }
    float inv = 1.f / red[0];

    for (int i = tid; i < O_; i += 256)
        out[(size_t)b * O_ + i] = expf(lr[i] - m) * inv;
}

// ---------------------------------------------------------------------------
extern "C" void kernel_launch(void* const* d_in, const int* in_sizes, int n_in,
                              void* d_out, int out_size)
{
    const float* x   = (const float*)d_in[0];  // [B,T,D]
    const float* Wx  = (const float*)d_in[1];  // [4,H,D]
    const float* Wh  = (const float*)d_in[2];  // [4,H,H]
    const float* b   = (const float*)d_in[3];  // [4,H]
    const float* Whp = (const float*)d_in[4];  // [O,H]
    const float* bhp = (const float*)d_in[5];  // [O]
    float* out = (float*)d_out;

    __half *x16, *wx_hi, *wx_lo, *wh_hi, *wh_lo;
    cudaGetSymbolAddress((void**)&x16,   g_x16);
    cudaGetSymbolAddress((void**)&wx_hi, g_Wx_hi);
    cudaGetSymbolAddress((void**)&wx_lo, g_Wx_lo);
    cudaGetSymbolAddress((void**)&wh_hi, g_Wh_hi);
    cudaGetSymbolAddress((void**)&wh_lo, g_Wh_lo);

    // 1) conversions
    {
        int nx = B_ * T_ * D_;
        cvt16_kernel<<<(nx + 255) / 256, 256>>>(x, x16, nx);
        int nwx = G4H * D_;
        split16_kernel<<<(nwx + 255) / 256, 256>>>(Wx, wx_hi, wx_lo, nwx);
        int nwh = G4H * H_;
        split16_kernel<<<(nwh + 255) / 256, 256>>>(Wh, wh_hi, wh_lo, nwh);
    }

    // 2) xproj = x @ Wx^T + b
    {
        dim3 grid(G4H / 32, (B_ * T_) / 128);
        xproj_kernel<<<grid, 256>>>(b);
    }

    // 3) init state + barrier
    init_kernel<<<(2 * B_ * H_ + 255) / 256, 256>>>();

    // 4) persistent recurrence (all 256 steps in one launch)
    cudaFuncSetAttribute(lstm_persistent_kernel,
                         cudaFuncAttributeMaxDynamicSharedMemorySize, SMEM_LSTM);
    lstm_persistent_kernel<<<NCTA, 128, SMEM_LSTM>>>();

    // 5) logits + softmax
    {
        dim3 grid(O_ / 64, B_ / 64);
        logits_gemm_kernel<<<grid, 256>>>(Whp, bhp);
    }
    softmax_kernel<<<B_, 256>>>(out);
}

// round 4
// speedup vs baseline: 5.2483x; 1.2678x over previous
#include <cuda_runtime.h>
#include <cuda_fp16.h>
#include <math.h>
#include <stdint.h>

#define B_   128
#define T_   256
#define D_   512
#define H_   1024
#define O_   1024
#define G4H  4096
#define NCTA 128

// ---------------- scratch (static device globals; no allocations) ----------
__device__ float g_xproj[(size_t)B_ * T_ * G4H];   // [B,T,4,H]
__device__ float g_h[B_ * H_];
__device__ float g_c[B_ * H_];
__device__ float g_logits[B_ * O_];
__device__ unsigned g_bar;

__device__ __align__(16) __half g_x16[(size_t)B_ * T_ * D_];
__device__ __align__(16) __half g_Wx16[G4H * D_];
__device__ __align__(16) __half g_Wh16[G4H * H_];
__device__ __align__(16) __half g_h16[2 * B_ * H_];   // ping-pong h (fp16)

// ---------------------------------------------------------------------------
// helpers
// ---------------------------------------------------------------------------
__device__ __forceinline__ uint32_t smem_u32(const void* p) {
    return (uint32_t)__cvta_generic_to_shared(p);
}

__device__ __forceinline__ void ldsm4(uint32_t& r0, uint32_t& r1, uint32_t& r2,
                                      uint32_t& r3, uint32_t a) {
    asm volatile("ldmatrix.sync.aligned.m8n8.x4.shared.b16 {%0,%1,%2,%3}, [%4];"
                 : "=r"(r0), "=r"(r1), "=r"(r2), "=r"(r3) : "r"(a));
}

__device__ __forceinline__ void mma_f16(float* c, const uint32_t* a,
                                        uint32_t b0, uint32_t b1) {
    asm volatile(
        "mma.sync.aligned.m16n8k16.row.col.f32.f16.f16.f32 "
        "{%0,%1,%2,%3}, {%4,%5,%6,%7}, {%8,%9}, {%0,%1,%2,%3};"
        : "+f"(c[0]), "+f"(c[1]), "+f"(c[2]), "+f"(c[3])
        : "r"(a[0]), "r"(a[1]), "r"(a[2]), "r"(a[3]), "r"(b0), "r"(b1));
}

__device__ __forceinline__ void cp_async16(uint32_t dst, const void* src) {
    asm volatile("cp.async.cg.shared.global [%0], [%1], 16;" :: "r"(dst), "l"(src));
}
__device__ __forceinline__ void cp_async8(uint32_t dst, const void* src) {
    asm volatile("cp.async.ca.shared.global [%0], [%1], 8;" :: "r"(dst), "l"(src));
}
__device__ __forceinline__ void cp_commit() {
    asm volatile("cp.async.commit_group;");
}
template <int N> __device__ __forceinline__ void cp_wait() {
    asm volatile("cp.async.wait_group %0;" :: "n"(N));
}

__device__ __forceinline__ float sigmoidf_(float x) {
    return 1.f / (1.f + __expf(-x));
}

// ---------------------------------------------------------------------------
// conversion kernels
// ---------------------------------------------------------------------------
__global__ void cvt16_kernel(const float* __restrict__ src,
                             __half* __restrict__ dst, int n)
{
    int i = blockIdx.x * blockDim.x + threadIdx.x;
    if (i < n) dst[i] = __float2half(src[i]);
}

__global__ void init_kernel()
{
    int i = blockIdx.x * blockDim.x + threadIdx.x;
    if (i < B_ * H_) g_c[i] = 0.f;
    if (i < 2 * B_ * H_) g_h16[i] = __float2half(0.f);
    if (i == 0) g_bar = 0;
}

// ---------------------------------------------------------------------------
// xproj GEMM: xproj[m,n] = x16[m,:] @ Wx16[n,:]^T + bias[n]
// M=32768, N=4096, K=512. CTA tile M128 N64 K32, 128 threads = 4 warps,
// warp tile m32 n64 (2 mi x 8 ni).
// ---------------------------------------------------------------------------
__global__ __launch_bounds__(128)
void xproj_kernel(const float* __restrict__ bias)
{
    __shared__ __align__(16) __half As[128 * 40];
    __shared__ __align__(16) __half Bs[64 * 40];

    const int tid  = threadIdx.x;
    const int lane = tid & 31;
    const int w    = tid >> 5;
    const int m_off = blockIdx.y * 128;
    const int n0    = blockIdx.x * 64;

    float acc[2][8][4];
    #pragma unroll
    for (int mi = 0; mi < 2; mi++)
        #pragma unroll
        for (int ni = 0; ni < 8; ni++)
            #pragma unroll
            for (int r = 0; r < 4; r++) acc[mi][ni][r] = 0.f;

    for (int k0 = 0; k0 < D_; k0 += 32) {
        #pragma unroll
        for (int ii = 0; ii < 4; ii++) {
            int i = tid + ii * 128;          // 0..511
            int row = i >> 2, q = i & 3;
            *(((uint4*)(As + row * 40)) + q) =
                *((const uint4*)(g_x16 + (size_t)(m_off + row) * D_ + k0) + q);
        }
        #pragma unroll
        for (int ii = 0; ii < 2; ii++) {
            int i = tid + ii * 128;          // 0..255
            int rr = i >> 2, q = i & 3;
            *(((uint4*)(Bs + rr * 40)) + q) =
                *((const uint4*)(g_Wx16 + (size_t)(n0 + rr) * D_ + k0) + q);
        }
        __syncthreads();

        #pragma unroll
        for (int kk = 0; kk < 32; kk += 16) {
            uint32_t a[2][4], b[8][2];
            int arow = lane & 15;
            int acol = kk + ((lane >> 4) << 3);
            #pragma unroll
            for (int mi = 0; mi < 2; mi++) {
                uint32_t ad = smem_u32(As + (w * 32 + mi * 16 + arow) * 40 + acol);
                ldsm4(a[mi][0], a[mi][1], a[mi][2], a[mi][3], ad);
            }
            int brl = ((lane >> 4) << 3) + (lane & 7);
            int bcol = kk + (((lane >> 3) & 1) << 3);
            #pragma unroll
            for (int g = 0; g < 4; g++) {
                uint32_t bd = smem_u32(Bs + (g * 16 + brl) * 40 + bcol);
                ldsm4(b[g * 2][0], b[g * 2][1], b[g * 2 + 1][0], b[g * 2 + 1][1], bd);
            }
            #pragma unroll
            for (int mi = 0; mi < 2; mi++)
                #pragma unroll
                for (int ni = 0; ni < 8; ni++)
                    mma_f16(acc[mi][ni], a[mi], b[ni][0], b[ni][1]);
        }
        __syncthreads();
    }

    #pragma unroll
    for (int mi = 0; mi < 2; mi++) {
        #pragma unroll
        for (int ni = 0; ni < 8; ni++) {
            int grow = m_off + w * 32 + mi * 16 + (lane >> 2);
            int gcol = n0 + ni * 8 + ((lane & 3) << 1);
            float b0 = bias[gcol], b1 = bias[gcol + 1];
            float* p0 = g_xproj + (size_t)grow * G4H + gcol;
            p0[0] = acc[mi][ni][0] + b0;
            p0[1] = acc[mi][ni][1] + b1;
            float* p1 = g_xproj + (size_t)(grow + 8) * G4H + gcol;
            p1[0] = acc[mi][ni][2] + b0;
            p1[1] = acc[mi][ni][3] + b1;
        }
    }
}

// ---------------------------------------------------------------------------
// Persistent LSTM recurrence kernel (single fp16 everywhere).
// 128 CTAs x 128 threads. CTA owns 8 h-cols x 4 gates (32 Wh rows, gate-major:
// smem B row r -> global Wh row (r>>3)*H + col0 + (r&7)).
// Wh fp16 resident in SMEM (66KB). h fp16 streamed per step via cp.async
// double buffer (K chunk = 64). xproj slice double-buffered, prefetched for
// t+1 before the grid barrier. Warp tile m32 n32.
// ---------------------------------------------------------------------------
#define WH_SZ     (32 * 1032 * 2)           // 66048
#define AS_OFF    WH_SZ
#define AS_BUF_SZ (128 * 72 * 2)            // 18432 per buffer
#define XP_OFF    (AS_OFF + 2 * AS_BUF_SZ)  // 102912
#define XP_SZ     (128 * 34 * 4)            // 17408 per buffer
#define SMEM_LSTM (XP_OFF + 2 * XP_SZ)      // 137728

__device__ __forceinline__ void load_chunk(uint32_t sbase, const __half* hin,
                                           int ch, int buf)
{
    const int tid = threadIdx.x;
    #pragma unroll
    for (int i = 0; i < 8; i++) {
        int idx = tid + i * 128;        // 0..1023
        int r = idx >> 3, c = idx & 7;
        cp_async16(sbase + AS_OFF + buf * AS_BUF_SZ + r * 144 + c * 16,
                   hin + (size_t)r * H_ + ch * 64 + c * 8);
    }
}

__device__ __forceinline__ void prefetch_xp(uint32_t sbase, int t, int buf,
                                            int col0)
{
    const int lane = threadIdx.x & 31;
    const int w    = threadIdx.x >> 5;
    int q2 = (lane & 3) * 2;
    #pragma unroll
    for (int mi = 0; mi < 2; mi++)
        #pragma unroll
        for (int ro = 0; ro < 2; ro++) {
            int b = w * 32 + mi * 16 + ro * 8 + (lane >> 2);
            #pragma unroll
            for (int g = 0; g < 4; g++) {
                const float* src = g_xproj +
                    (((size_t)b * T_ + t) * 4 + g) * H_ + col0 + q2;
                cp_async8(sbase + XP_OFF + buf * XP_SZ + (b * 34 + g * 8 + q2) * 4,
                          src);
            }
        }
}

__global__ __launch_bounds__(128, 1)
void lstm_persistent_kernel()
{
    extern __shared__ char sm[];
    const int tid  = threadIdx.x;
    const int lane = tid & 31;
    const int w    = tid >> 5;
    const int col0 = blockIdx.x * 8;
    const uint32_t sbase = smem_u32(sm);

    // ---- resident Wh load (fp16 single) ----
    for (int i = tid; i < 4096; i += 128) {
        int r = i >> 7;
        int c = i & 127;
        int ng = (r >> 3) * H_ + col0 + (r & 7);
        cp_async16(sbase + r * 2064 + c * 16, g_Wh16 + (size_t)ng * H_ + c * 8);
    }
    // ---- xproj slice for step 0 ----
    prefetch_xp(sbase, 0, 0, col0);
    cp_commit();

    for (int t = 0; t < T_; ++t) {
        const __half* hin = g_h16 + (size_t)(t & 1) * (B_ * H_);

        load_chunk(sbase, hin, 0, 0);
        cp_commit();

        float acc[2][4][4];
        #pragma unroll
        for (int mi = 0; mi < 2; mi++)
            #pragma unroll
            for (int ni = 0; ni < 4; ni++)
                #pragma unroll
                for (int r = 0; r < 4; r++) acc[mi][ni][r] = 0.f;

        for (int ch = 0; ch < 16; ++ch) {
            if (ch < 15) {
                load_chunk(sbase, hin, ch + 1, (ch + 1) & 1);
                cp_commit();
                cp_wait<1>();
            } else {
                cp_wait<0>();
            }
            __syncthreads();

            #pragma unroll
            for (int kk = 0; kk < 64; kk += 16) {
                uint32_t a[2][4];
                #pragma unroll
                for (int mi = 0; mi < 2; mi++) {
                    uint32_t ad = sbase + AS_OFF + (ch & 1) * AS_BUF_SZ
                                + (w * 32 + mi * 16 + (lane & 15)) * 144
                                + (kk + ((lane >> 4) << 3)) * 2;
                    ldsm4(a[mi][0], a[mi][1], a[mi][2], a[mi][3], ad);
                }
                uint32_t b[4][2];
                #pragma unroll
                for (int nh = 0; nh < 2; nh++) {
                    int row = nh * 16 + ((lane >> 4) << 3) + (lane & 7);
                    int cb  = (ch * 64 + kk + (((lane >> 3) & 1) << 3)) * 2;
                    ldsm4(b[nh * 2][0], b[nh * 2][1],
                          b[nh * 2 + 1][0], b[nh * 2 + 1][1],
                          sbase + row * 2064 + cb);
                }
                #pragma unroll
                for (int mi = 0; mi < 2; mi++)
                    #pragma unroll
                    for (int ni = 0; ni < 4; ni++)
                        mma_f16(acc[mi][ni], a[mi], b[ni][0], b[ni][1]);
            }
            __syncthreads();
        }

        // ---- register-resident LSTM epilogue ----
        __half* hout = g_h16 + (size_t)((t + 1) & 1) * (B_ * H_);
        const float* xps = (const float*)(sm + XP_OFF + (t & 1) * XP_SZ);
        #pragma unroll
        for (int mi = 0; mi < 2; mi++)
            #pragma unroll
            for (int ro = 0; ro < 2; ro++) {
                int b  = w * 32 + mi * 16 + ro * 8 + (lane >> 2);
                int q2 = (lane & 3) * 2;
                const float* xpb = xps + b * 34;
                int idx = b * H_ + col0 + q2;
                float2 cold = *(const float2*)(g_c + idx);
                float cv[2], hv[2];
                #pragma unroll
                for (int j = 0; j < 2; j++) {
                    int f = ro * 2 + j;
                    float gi = acc[mi][0][f] + xpb[q2 + j];
                    float gf = acc[mi][1][f] + xpb[8 + q2 + j];
                    float gg = acc[mi][2][f] + xpb[16 + q2 + j];
                    float go = acc[mi][3][f] + xpb[24 + q2 + j];
                    float it = sigmoidf_(gi);
                    float ft = sigmoidf_(gf);
                    float gt = tanhf(gg);
                    float ot = sigmoidf_(go);
                    float c  = ft * (j ? cold.y : cold.x) + it * gt;
                    cv[j] = c;
                    hv[j] = ot * tanhf(c);
                }
                *(float2*)(g_c + idx) = make_float2(cv[0], cv[1]);
                *(__half2*)(hout + idx) = __floats2half2_rn(hv[0], hv[1]);
                if (t == T_ - 1)
                    *(float2*)(g_h + idx) = make_float2(hv[0], hv[1]);
            }

        // ---- prefetch next step's xproj slice (h-independent) ----
        if (t < T_ - 1) {
            prefetch_xp(sbase, t + 1, (t + 1) & 1, col0);
            cp_commit();
        }

        // ---- software grid barrier ----
        __syncthreads();
        if (tid == 0) {
            __threadfence();
            atomicAdd(&g_bar, 1u);
            unsigned tgt = (unsigned)NCTA * (t + 1);
            unsigned v;
            do {
                asm volatile("ld.acquire.gpu.u32 %0, [%1];" : "=r"(v) : "l"(&g_bar));
            } while (v < tgt);
        }
        __syncthreads();
    }
}

// ---------------------------------------------------------------------------
// Logits GEMM (fp32): C[128,1024] = g_h @ Whp^T + bhp
// ---------------------------------------------------------------------------
__global__ __launch_bounds__(256)
void logits_gemm_kernel(const float* __restrict__ Bm,
                        const float* __restrict__ bias)
{
    __shared__ float As[16][65];
    __shared__ float Bs[16][65];

    const int bn = blockIdx.x;
    const int bm = blockIdx.y;
    const int tid = threadIdx.x;
    const int tx = tid & 15;
    const int ty = tid >> 4;

    const float* Ab = g_h + (size_t)bm * 64 * H_;
    const float* Bb = Bm  + (size_t)bn * 64 * H_;

    const int lrow = tid >> 2;
    const int lk   = (tid & 3) * 4;

    float acc[4][4];
    #pragma unroll
    for (int i = 0; i < 4; i++)
        #pragma unroll
        for (int j = 0; j < 4; j++) acc[i][j] = 0.f;

    for (int k0 = 0; k0 < H_; k0 += 16) {
        float4 av = *(const float4*)(Ab + (size_t)lrow * H_ + k0 + lk);
        float4 bv = *(const float4*)(Bb + (size_t)lrow * H_ + k0 + lk);
        As[lk + 0][lrow] = av.x; As[lk + 1][lrow] = av.y;
        As[lk + 2][lrow] = av.z; As[lk + 3][lrow] = av.w;
        Bs[lk + 0][lrow] = bv.x; Bs[lk + 1][lrow] = bv.y;
        Bs[lk + 2][lrow] = bv.z; Bs[lk + 3][lrow] = bv.w;
        __syncthreads();

        #pragma unroll
        for (int kk = 0; kk < 16; kk++) {
            float am[4], bnv[4];
            #pragma unroll
            for (int i = 0; i < 4; i++) am[i]  = As[kk][ty * 4 + i];
            #pragma unroll
            for (int j = 0; j < 4; j++) bnv[j] = Bs[kk][tx * 4 + j];
            #pragma unroll
            for (int i = 0; i < 4; i++)
                #pragma unroll
                for (int j = 0; j < 4; j++)
                    acc[i][j] = fmaf(am[i], bnv[j], acc[i][j]);
        }
        __syncthreads();
    }

    const int row0 = bm * 64 + ty * 4;
    const int col0 = bn * 64 + tx * 4;
    #pragma unroll
    for (int i = 0; i < 4; i++)
        #pragma unroll
        for (int j = 0; j < 4; j++)
            g_logits[(size_t)(row0 + i) * O_ + col0 + j] = acc[i][j] + bias[col0 + j];
}

// ---------------------------------------------------------------------------
// Softmax rows -> output
// ---------------------------------------------------------------------------
__global__ __launch_bounds__(256)
void softmax_kernel(float* __restrict__ out)
{
    __shared__ float red[256];
    const int b = blockIdx.x;
    const int tid = threadIdx.x;
    const float* lr = g_logits + (size_t)b * O_;

    float m = -INFINITY;
    for (int i = tid; i < O_; i += 256) m = fmaxf(m, lr[i]);
    red[tid] = m; __syncthreads();
    for (int s = 128; s > 0; s >>= 1) {
        if (tid < s) red[tid] = fmaxf(red[tid], red[tid + s]);
        __syncthreads();
    }
    m = red[0]; __syncthreads();

    float sum = 0.f;
    for (int i = tid; i < O_; i += 256) sum += expf(lr[i] - m);
    red[tid] = sum; __syncthreads();
    for (int s = 128; s > 0; s >>= 1) {
        if (tid < s) red[tid] += red[tid + s];
        __syncthreads();
    }
    float inv = 1.f / red[0];

    for (int i = tid; i < O_; i += 256)
        out[(size_t)b * O_ + i] = expf(lr[i] - m) * inv;
}

// ---------------------------------------------------------------------------
extern "C" void kernel_launch(void* const* d_in, const int* in_sizes, int n_in,
                              void* d_out, int out_size)
{
    const float* x   = (const float*)d_in[0];  // [B,T,D]
    const float* Wx  = (const float*)d_in[1];  // [4,H,D]
    const float* Wh  = (const float*)d_in[2];  // [4,H,H]
    const float* b   = (const float*)d_in[3];  // [4,H]
    const float* Whp = (const float*)d_in[4];  // [O,H]
    const float* bhp = (const float*)d_in[5];  // [O]
    float* out = (float*)d_out;

    __half *x16, *wx16, *wh16;
    cudaGetSymbolAddress((void**)&x16,  g_x16);
    cudaGetSymbolAddress((void**)&wx16, g_Wx16);
    cudaGetSymbolAddress((void**)&wh16, g_Wh16);

    // 1) conversions to fp16
    {
        int nx = B_ * T_ * D_;
        cvt16_kernel<<<(nx + 255) / 256, 256>>>(x, x16, nx);
        int nwx = G4H * D_;
        cvt16_kernel<<<(nwx + 255) / 256, 256>>>(Wx, wx16, nwx);
        int nwh = G4H * H_;
        cvt16_kernel<<<(nwh + 255) / 256, 256>>>(Wh, wh16, nwh);
    }

    // 2) xproj = x @ Wx^T + b
    {
        dim3 grid(G4H / 64, (B_ * T_) / 128);
        xproj_kernel<<<grid, 128>>>(b);
    }

    // 3) init state + barrier
    init_kernel<<<(2 * B_ * H_ + 255) / 256, 256>>>();

    // 4) persistent recurrence (all 256 steps in one launch)
    cudaFuncSetAttribute(lstm_persistent_kernel,
                         cudaFuncAttributeMaxDynamicSharedMemorySize, SMEM_LSTM);
    lstm_persistent_kernel<<<NCTA, 128, SMEM_LSTM>>>();

    // 5) logits + softmax
    {
        dim3 grid(O_ / 64, B_ / 64);
        logits_gemm_kernel<<<grid, 256>>>(Whp, bhp);
    }
    softmax_kernel<<<B_, 256>>>(out);
}